// round 1
// baseline (speedup 1.0000x reference)
#include <cuda_runtime.h>
#include <cstddef>

#define NBLK        148
#define OUT_FEAT    1024
#define BATCH       32
#define ACC_STRIDE  1056   // 1024 bins + 32 dummy slots for tail lanes

// Partial sums: one [32][1024] tile per block. 148*32*1024*4 = 19.4 MB.
__device__ float g_part[(size_t)NBLK * BATCH * OUT_FEAT];

__global__ __launch_bounds__(1024, 1)
void hash_scatter_kernel(const float* __restrict__ x,
                         const int*   __restrict__ sel,
                         const float* __restrict__ sign,
                         int N)
{
    extern __shared__ float acc[];          // [BATCH][ACC_STRIDE]
    const int tid  = threadIdx.x;
    const int lane = tid & 31;
    const int w    = tid >> 5;              // warp id == batch index
    float* wacc = acc + w * ACC_STRIDE;

    // Zero the per-warp accumulators
    for (int i = tid; i < BATCH * ACC_STRIDE; i += 1024) acc[i] = 0.0f;
    __syncthreads();

    const int numQuads   = N >> 2;                    // N % 4 == 0 (N = 1e6)
    const int totalTiles = (numQuads + 31) >> 5;      // 128 columns per tile
    const int tilesPerBlock = (totalTiles + NBLK - 1) / NBLK;
    const int t0 = blockIdx.x * tilesPerBlock;
    const int t1 = (t0 + tilesPerBlock < totalTiles) ? (t0 + tilesPerBlock) : totalTiles;

    const float4* __restrict__ x4 = reinterpret_cast<const float4*>(x + (size_t)w * N);
    const int4*   __restrict__ s4 = reinterpret_cast<const int4*>(sel);
    const float4* __restrict__ g4 = reinterpret_cast<const float4*>(sign);

    const unsigned FULL   = 0xffffffffu;
    const unsigned ltmask = (1u << lane) - 1u;

    for (int t = t0; t < t1; ++t) {
        const int qi = (t << 5) + lane;     // quad index for this lane
        float4 xv, gv; int4 sv;
        if (qi < numQuads) {
            xv = x4[qi]; sv = s4[qi]; gv = g4[qi];
        } else {
            xv = make_float4(0.f, 0.f, 0.f, 0.f);
            gv = xv;
            const int d = OUT_FEAT + lane;  // unique dummy bin per lane
            sv = make_int4(d, d, d, d);
        }

        float vv[4] = {xv.x * gv.x, xv.y * gv.y, xv.z * gv.z, xv.w * gv.w};
        int   ss[4] = {sv.x, sv.y, sv.z, sv.w};

        #pragma unroll
        for (int j = 0; j < 4; ++j) {
            int   s = ss[j];
            float v = vv[j];
            // Partition lanes by bin
            const unsigned m = __match_any_sync(FULL, s);
            const int rank  = __popc(m & ltmask);     // position within group
            const int gsize = __popc(m);
            const int maxg  = __reduce_max_sync(FULL, gsize);  // uniform trip count
            // Leader gathers the group's values (usually maxg == 1 -> loop skipped)
            for (int r = 1; r < maxg; ++r) {
                const int src = __fns(m, 0, r + 1);   // (r+1)-th set bit, -1 if none
                const float tv = __shfl_sync(FULL, v, (src < 0) ? 0 : src);
                if (rank == 0 && r < gsize) v += tv;
            }
            // One lane per distinct bin -> conflict-free non-atomic RMW
            if (rank == 0) wacc[s] += v;
        }
    }
    __syncthreads();

    // Flush this block's partials (coalesced: lanes stride the bin dimension)
    float* dst = g_part + ((size_t)blockIdx.x * BATCH + w) * OUT_FEAT;
    for (int o = lane; o < OUT_FEAT; o += 32) dst[o] = wacc[o];
}

__global__ void reduce_kernel(float* __restrict__ out)
{
    const int j = blockIdx.x * blockDim.x + threadIdx.x;   // 0 .. 32767
    float s = 0.0f;
    #pragma unroll 4
    for (int b = 0; b < NBLK; ++b)
        s += g_part[(size_t)b * (BATCH * OUT_FEAT) + j];
    out[j] = s;
}

extern "C" void kernel_launch(void* const* d_in, const int* in_sizes, int n_in,
                              void* d_out, int out_size)
{
    const float* x    = (const float*)d_in[0];
    const int*   sel  = (const int*)  d_in[1];
    const float* sign = (const float*)d_in[2];
    const int N = in_sizes[1];                 // sel element count

    const int smem = BATCH * ACC_STRIDE * (int)sizeof(float);
    cudaFuncSetAttribute(hash_scatter_kernel,
                         cudaFuncAttributeMaxDynamicSharedMemorySize, smem);

    hash_scatter_kernel<<<NBLK, 1024, smem>>>(x, sel, sign, N);
    reduce_kernel<<<(BATCH * OUT_FEAT) / 256, 256>>>((float*)d_out);
}

// round 5
// speedup vs baseline: 2.9116x; 2.9116x over previous
#include <cuda_runtime.h>
#include <cstddef>

#define NBLK        148
#define OUT_FEAT    1024
#define BATCH       32
#define NWARP       8              // warps per block; warp w owns batches 4w..4w+3
#define ACC_BINS    (OUT_FEAT + 32)   // 32 dummy bins for tail lanes
#define ACC_STRIDE  36             // words per bin row: 32 batches + 4 pad (bank swizzle)

// Per-block partials: [block][batch][out] = 148 * 32 * 1024 * 4B = 19.4 MB
__device__ float g_part[(size_t)NBLK * BATCH * OUT_FEAT];

__global__ void dummy_kernel() {}

__global__ __launch_bounds__(256, 1)
void hash_kernel(const float* __restrict__ x,
                 const int*   __restrict__ sel,
                 const float* __restrict__ sign,
                 int N)
{
    extern __shared__ float acc[];          // [ACC_BINS][ACC_STRIDE]
    const int tid  = threadIdx.x;
    const int lane = tid & 31;
    const int w    = tid >> 5;              // warp id -> batches 4w..4w+3
    const unsigned FULL   = 0xffffffffu;
    const unsigned ltmask = (1u << lane) - 1u;

    for (int i = tid; i < ACC_BINS * ACC_STRIDE; i += 256) acc[i] = 0.0f;
    __syncthreads();

    const int numQuads   = N >> 2;                 // N % 4 == 0
    const int totalTiles = (numQuads + 31) >> 5;   // 32 quads (=128 cols) per tile
    const int tpb = (totalTiles + NBLK - 1) / NBLK;
    const int t0  = blockIdx.x * tpb;
    const int t1  = (t0 + tpb < totalTiles) ? (t0 + tpb) : totalTiles;

    const int4*   __restrict__ s4 = reinterpret_cast<const int4*>(sel);
    const float4* __restrict__ g4 = reinterpret_cast<const float4*>(sign);
    const float4* __restrict__ x0 = reinterpret_cast<const float4*>(x + (size_t)(4*w+0) * N);
    const float4* __restrict__ x1 = reinterpret_cast<const float4*>(x + (size_t)(4*w+1) * N);
    const float4* __restrict__ x2 = reinterpret_cast<const float4*>(x + (size_t)(4*w+2) * N);
    const float4* __restrict__ x3 = reinterpret_cast<const float4*>(x + (size_t)(4*w+3) * N);

    if (t0 >= t1) { __syncthreads(); goto flush; }

    {
        // ---- software pipeline: prefetch tile t+1 while RMW-ing tile t ----
        int4 sv; float4 gv, a0, a1, a2, a3;
        {
            const int qi = (t0 << 5) + lane;
            if (qi < numQuads) {
                sv = s4[qi]; gv = g4[qi];
                a0 = x0[qi]; a1 = x1[qi]; a2 = x2[qi]; a3 = x3[qi];
            } else {
                const int d = OUT_FEAT + lane;
                sv = make_int4(d, d, d, d);
                gv = make_float4(0.f, 0.f, 0.f, 0.f);
                a0 = a1 = a2 = a3 = gv;
            }
        }

        for (int t = t0; t < t1; ++t) {
            int4 sv_c = sv; float4 gv_c = gv;
            float4 b0 = a0, b1 = a1, b2 = a2, b3 = a3;

            if (t + 1 < t1) {                   // prefetch next tile
                const int qi = ((t + 1) << 5) + lane;
                if (qi < numQuads) {
                    sv = s4[qi]; gv = g4[qi];
                    a0 = x0[qi]; a1 = x1[qi]; a2 = x2[qi]; a3 = x3[qi];
                } else {
                    const int d = OUT_FEAT + lane;
                    sv = make_int4(d, d, d, d);
                    gv = make_float4(0.f, 0.f, 0.f, 0.f);
                    a0 = a1 = a2 = a3 = gv;
                }
            }

            const int   ss[4] = {sv_c.x, sv_c.y, sv_c.z, sv_c.w};
            const float gg[4] = {gv_c.x, gv_c.y, gv_c.z, gv_c.w};
            const float r0[4] = {b0.x, b0.y, b0.z, b0.w};
            const float r1[4] = {b1.x, b1.y, b1.z, b1.w};
            const float r2[4] = {b2.x, b2.y, b2.z, b2.w};
            const float r3[4] = {b3.x, b3.y, b3.z, b3.w};

            #pragma unroll
            for (int j = 0; j < 4; ++j) {
                const int   s = ss[j];
                const float g = gg[j];
                const float v0 = r0[j] * g;
                const float v1 = r1[j] * g;
                const float v2 = r2[j] * g;
                const float v3 = r3[j] * g;

                // dedup intra-warp duplicate bins: rank-retry passes
                const unsigned m    = __match_any_sync(FULL, s);
                const int      rank = __popc(m & ltmask);
                const int      maxg = __reduce_max_sync(FULL, __popc(m));

                float* p = acc + s * ACC_STRIDE + 4 * w;   // 16B-aligned
                for (int r = 0; r < maxg; ++r) {
                    if (rank == r) {
                        float4 o = *reinterpret_cast<float4*>(p);
                        o.x += v0; o.y += v1; o.z += v2; o.w += v3;
                        *reinterpret_cast<float4*>(p) = o;
                    }
                }
            }
        }
    }
    __syncthreads();

flush:
    // flush partials: g_part[block][b][o] = acc[o][b]  (STG coalesced)
    {
        float* dst = g_part + (size_t)blockIdx.x * (BATCH * OUT_FEAT);
        for (int idx = tid; idx < BATCH * OUT_FEAT; idx += 256) {
            const int b = idx >> 10;           // OUT_FEAT = 1024
            const int o = idx & (OUT_FEAT - 1);
            dst[idx] = acc[o * ACC_STRIDE + b];
        }
    }
}

__global__ __launch_bounds__(256)
void reduce_kernel(float* __restrict__ out)
{
    const int j = blockIdx.x * 256 + threadIdx.x;   // 0 .. 32767
    float s0 = 0.f, s1 = 0.f, s2 = 0.f, s3 = 0.f;
    int b = 0;
    #pragma unroll 4
    for (; b + 4 <= NBLK; b += 4) {
        s0 += g_part[(size_t)(b + 0) * (BATCH * OUT_FEAT) + j];
        s1 += g_part[(size_t)(b + 1) * (BATCH * OUT_FEAT) + j];
        s2 += g_part[(size_t)(b + 2) * (BATCH * OUT_FEAT) + j];
        s3 += g_part[(size_t)(b + 3) * (BATCH * OUT_FEAT) + j];
    }
    for (; b < NBLK; ++b)
        s0 += g_part[(size_t)b * (BATCH * OUT_FEAT) + j];
    out[j] = (s0 + s1) + (s2 + s3);
}

extern "C" void kernel_launch(void* const* d_in, const int* in_sizes, int n_in,
                              void* d_out, int out_size)
{
    const float* x    = (const float*)d_in[0];
    const int*   sel  = (const int*)  d_in[1];
    const float* sign = (const float*)d_in[2];
    const int N = in_sizes[1];     // sel element count = 1e6

    const int smem = ACC_BINS * ACC_STRIDE * (int)sizeof(float);   // ~152 KB
    cudaFuncSetAttribute(hash_kernel,
                         cudaFuncAttributeMaxDynamicSharedMemorySize, smem);

    // Launch order [dummy, hash, reduce, dummy] puts hash_kernel at global
    // launch index 5 so ncu (-s 5 -c 1) profiles the kernel that matters.
    dummy_kernel<<<1, 32>>>();
    hash_kernel<<<NBLK, 256, smem>>>(x, sel, sign, N);
    reduce_kernel<<<(BATCH * OUT_FEAT) / 256, 256>>>((float*)d_out);
    dummy_kernel<<<1, 32>>>();
}